// round 9
// baseline (speedup 1.0000x reference)
#include <cuda_runtime.h>
#include <stdint.h>

#define N_NODES 50000
#define N_EDGES 800000
#define F_HID 128
#define F_OUT 40
#define NB_NODE 196   /* ceil(50000/256) */
#define NB_EDGE 3125  /* 800000/256 */
#define HALF_N 25000

// ---------------- device scratch ----------------
__device__ __align__(16) int   g_row[N_EDGES];
__device__ __align__(16) int   g_col[N_EDGES];
__device__ __align__(16) float g_ewc[N_EDGES];
__device__ __align__(16) float g_deg[N_NODES];
__device__ __align__(16) float g_dinv[N_NODES];
__device__ __align__(16) int   g_count[N_NODES];
__device__ __align__(16) int   g_fill[N_NODES];
__device__ __align__(16) int   g_mint[N_NODES];
__device__ __align__(16) int   g_rowptr[N_NODES + 1];
__device__ __align__(16) int   g_outpos[N_NODES];
__device__ volatile unsigned long long g_bsum[256];
__device__ __align__(16) int2  g_csr[N_EDGES];
__device__ __align__(16) float g_hA[(size_t)N_NODES * F_HID];
__device__ __align__(16) float g_hB[(size_t)N_NODES * F_HID];
__device__ __align__(16) float g_hC[(size_t)N_NODES * F_OUT];
__device__ int g_is64;

// ---------------- packed f32x2 helpers (Blackwell FFMA2) ----------------
__device__ __forceinline__ unsigned long long pack2(float lo, float hi) {
    unsigned long long r;
    asm("mov.b64 %0, {%1, %2};" : "=l"(r) : "f"(lo), "f"(hi));
    return r;
}
__device__ __forceinline__ void ffma2(unsigned long long& d,
                                      unsigned long long a,
                                      unsigned long long b) {
    asm("fma.rn.f32x2 %0, %1, %2, %0;" : "+l"(d) : "l"(a), "l"(b));
}
__device__ __forceinline__ float2 unpack2(unsigned long long v) {
    float lo, hi;
    asm("mov.b64 {%0, %1}, %2;" : "=f"(lo), "=f"(hi) : "l"(v));
    return make_float2(lo, hi);
}

// ---------------- fused init: probe + zero + mask decode ----------------
__global__ void k_prep0(const void* mask_, const void* ei_) {
    int i = blockIdx.x * blockDim.x + threadIdx.x;
    if (i == 0) {
        const long long* p = (const long long*)ei_;
        int ok = 1;
        #pragma unroll 1
        for (int k = 0; k < 64; ++k) {
            long long v = p[k];
            if (v < 0 || v >= N_NODES) { ok = 0; break; }
        }
        g_is64 = ok;
    }
    if (i < 256) g_bsum[i] = 0ull;
    if (i < N_NODES) {
        g_deg[i] = 0.0f;
        g_count[i] = 0;
        g_fill[i] = 0;
        unsigned int w0 = ((const unsigned int*)mask_)[0];
        int m;
        if (w0 == 1u) m = (((const int*)mask_)[i] != 0) ? 1 : 0;
        else          m = (((const unsigned char*)mask_)[i] != 0) ? 1 : 0;
        g_mint[i] = m;
    }
}

__global__ void k_edge_prep(const void* ei_, const float* __restrict__ ew) {
    int e = blockIdx.x * blockDim.x + threadIdx.x;
    if (e < N_EDGES) {
        int r, c;
        if (g_is64) {
            const long long* ei = (const long long*)ei_;
            r = (int)ei[e];
            c = (int)ei[N_EDGES + e];
        } else {
            const int* ei = (const int*)ei_;
            r = ei[e];
            c = ei[N_EDGES + e];
        }
        r = min(max(r, 0), N_NODES - 1);
        c = min(max(c, 0), N_NODES - 1);
        float w = ew[e];
        g_row[e] = r;
        g_col[e] = c;
        g_ewc[e] = w;
        atomicAdd(&g_deg[c], w);
        atomicAdd(&g_count[c], 1);
    }
}

// ---------------- single-kernel dual scan (decoupled lookback) ----------------
// Safe: 196 blocks all co-resident (256 thr, tiny smem); each block publishes
// its totals without waiting on any other block.
__global__ void k_scan_fused() {
    __shared__ int sa[256], sb[256];
    __shared__ int s_prefA, s_prefB;
    const int t = threadIdx.x;
    const int bid = blockIdx.x;
    const int i = bid * 256 + t;
    int va = (i < N_NODES) ? g_count[i] : 0;
    int vb = (i < N_NODES) ? g_mint[i] : 0;
    sa[t] = va; sb[t] = vb;
    __syncthreads();
    for (int off = 1; off < 256; off <<= 1) {
        int aa = (t >= off) ? sa[t - off] : 0;
        int ab = (t >= off) ? sb[t - off] : 0;
        __syncthreads();
        sa[t] += aa; sb[t] += ab;
        __syncthreads();
    }
    // publish packed block totals (flag = totalA+1 in low word; totals < 2^31)
    if (t == 255) {
        unsigned long long v = ((unsigned long long)(unsigned)sb[255] << 32)
                             | (unsigned)(sa[255] + 1);
        g_bsum[bid] = v;
    }
    // lookback over predecessors (warp 0)
    if (t < 32) {
        int pA = 0, pB = 0;
        for (int p = t; p < bid; p += 32) {
            unsigned long long v;
            do { v = g_bsum[p]; } while ((unsigned)v == 0u);
            pA += (int)((unsigned)v) - 1;
            pB += (int)(v >> 32);
        }
        #pragma unroll
        for (int off = 16; off > 0; off >>= 1) {
            pA += __shfl_down_sync(0xffffffffu, pA, off);
            pB += __shfl_down_sync(0xffffffffu, pB, off);
        }
        if (t == 0) { s_prefA = pA; s_prefB = pB; }
    }
    __syncthreads();
    if (i < N_NODES) {
        g_rowptr[i] = s_prefA + sa[t] - va;
        g_outpos[i] = s_prefB + sb[t] - vb;
        g_dinv[i] = rsqrtf(g_deg[i] + 1.0f);
    }
    if (bid == NB_NODE - 1 && t == 255) {
        g_rowptr[N_NODES] = s_prefA + sa[255];
    }
}

__global__ void k_scatter() {
    int e = blockIdx.x * blockDim.x + threadIdx.x;
    if (e < N_EDGES) {
        int c = g_col[e];
        int r = g_row[e];
        int pos = g_rowptr[c] + atomicAdd(&g_fill[c], 1);
        float nrm = g_dinv[r] * g_ewc[e] * g_dinv[c];
        g_csr[pos] = make_int2(r, __float_as_int(nrm));
    }
}

// ---------------- GEMM 128x128 (FFMA2), row range [rbase, rend) ----------------
__global__ void k_gemm128(const float* __restrict__ X, const float* __restrict__ W,
                          float* __restrict__ H, int rbase, int rend) {
    extern __shared__ float smdyn[];
    float* sW = smdyn;
    float* sX = smdyn + 128 * 128;
    const int tid = threadIdx.x;

    float4* sW4 = (float4*)sW;
    const float4* W4 = (const float4*)W;
    #pragma unroll
    for (int i = 0; i < 16; ++i) sW4[tid + 256 * i] = W4[tid + 256 * i];

    const int row0 = rbase + blockIdx.x * 64;
    float4* sX4 = (float4*)sX;
    #pragma unroll
    for (int i = 0; i < 8; ++i) {
        int idx = tid + 256 * i;
        int r = idx >> 5, c = idx & 31;
        int gr = min(row0 + r, rend - 1);
        sX4[idx] = ((const float4*)(X + (size_t)gr * 128))[c];
    }
    __syncthreads();

    const int tx = tid & 15;
    const int ty = tid >> 4;

    unsigned long long acc[4][4];
    #pragma unroll
    for (int r = 0; r < 4; ++r)
        #pragma unroll
        for (int c = 0; c < 4; ++c) acc[r][c] = 0ull;

    const float* xbase = sX + (4 * ty) * 128;
    const float* wbase = sW + 8 * tx;

    #pragma unroll 4
    for (int k4 = 0; k4 < 32; ++k4) {
        float4 xr0 = *(const float4*)(xbase + 0 * 128 + 4 * k4);
        float4 xr1 = *(const float4*)(xbase + 1 * 128 + 4 * k4);
        float4 xr2 = *(const float4*)(xbase + 2 * 128 + 4 * k4);
        float4 xr3 = *(const float4*)(xbase + 3 * 128 + 4 * k4);
        #pragma unroll
        for (int kk = 0; kk < 4; ++kk) {
            const float* wrow = wbase + (4 * k4 + kk) * 128;
            ulonglong2 w01 = *(const ulonglong2*)(wrow);
            ulonglong2 w23 = *(const ulonglong2*)(wrow + 4);
            float x0 = (&xr0.x)[kk];
            float x1 = (&xr1.x)[kk];
            float x2 = (&xr2.x)[kk];
            float x3 = (&xr3.x)[kk];
            unsigned long long p0 = pack2(x0, x0);
            unsigned long long p1 = pack2(x1, x1);
            unsigned long long p2 = pack2(x2, x2);
            unsigned long long p3 = pack2(x3, x3);
            ffma2(acc[0][0], p0, w01.x); ffma2(acc[0][1], p0, w01.y);
            ffma2(acc[0][2], p0, w23.x); ffma2(acc[0][3], p0, w23.y);
            ffma2(acc[1][0], p1, w01.x); ffma2(acc[1][1], p1, w01.y);
            ffma2(acc[1][2], p1, w23.x); ffma2(acc[1][3], p1, w23.y);
            ffma2(acc[2][0], p2, w01.x); ffma2(acc[2][1], p2, w01.y);
            ffma2(acc[2][2], p2, w23.x); ffma2(acc[2][3], p2, w23.y);
            ffma2(acc[3][0], p3, w01.x); ffma2(acc[3][1], p3, w01.y);
            ffma2(acc[3][2], p3, w23.x); ffma2(acc[3][3], p3, w23.y);
        }
    }

    const int cg = 8 * tx;
    #pragma unroll
    for (int r = 0; r < 4; ++r) {
        int gr = row0 + 4 * ty + r;
        if (gr < rend) {
            float2 q0 = unpack2(acc[r][0]);
            float2 q1 = unpack2(acc[r][1]);
            float2 q2 = unpack2(acc[r][2]);
            float2 q3 = unpack2(acc[r][3]);
            float4* dst = (float4*)(H + (size_t)gr * 128 + cg);
            dst[0] = make_float4(q0.x, q0.y, q1.x, q1.y);
            dst[1] = make_float4(q2.x, q2.y, q3.x, q3.y);
        }
    }
}

// ---------------- GEMM small-N (layer 3, N=40), row range ----------------
__global__ void k_gemm_small(const float* __restrict__ X, const float* __restrict__ W,
                             float* __restrict__ H, int rbase, int rend, int N) {
    __shared__ float sW[128 * 64];
    const int tid = threadIdx.x;
    const int sw = N;

    for (int i = tid; i < 128 * sw; i += 256) {
        int k = i / sw, c = i - k * sw;
        sW[k * 64 + c] = W[k * N + c];
    }
    __syncthreads();

    const int warp = tid >> 5;
    const int lane = tid & 31;
    const int r0 = rbase + blockIdx.x * 32 + warp * 4;
    const int myc = lane * 2;
    if (myc >= sw) return;

    const float* x0 = X + (size_t)min(r0 + 0, rend - 1) * 128;
    const float* x1 = X + (size_t)min(r0 + 1, rend - 1) * 128;
    const float* x2 = X + (size_t)min(r0 + 2, rend - 1) * 128;
    const float* x3 = X + (size_t)min(r0 + 3, rend - 1) * 128;

    float2 a0 = {0.f, 0.f}, a1 = a0, a2 = a0, a3 = a0;
    #pragma unroll 8
    for (int k = 0; k < 128; ++k) {
        float w0 = sW[k * 64 + myc];
        float w1 = sW[k * 64 + myc + 1];
        float v0 = __ldg(x0 + k), v1 = __ldg(x1 + k);
        float v2 = __ldg(x2 + k), v3 = __ldg(x3 + k);
        a0.x += v0 * w0; a0.y += v0 * w1;
        a1.x += v1 * w0; a1.y += v1 * w1;
        a2.x += v2 * w0; a2.y += v2 * w1;
        a3.x += v3 * w0; a3.y += v3 * w1;
    }

    if (r0 + 0 < rend) *(float2*)(H + (size_t)(r0 + 0) * N + myc) = a0;
    if (r0 + 1 < rend) *(float2*)(H + (size_t)(r0 + 1) * N + myc) = a1;
    if (r0 + 2 < rend) *(float2*)(H + (size_t)(r0 + 2) * N + myc) = a2;
    if (r0 + 3 < rend) *(float2*)(H + (size_t)(r0 + 3) * N + myc) = a3;
}

// ---------------- pull aggregation (warp/node, float4, x4 unroll), node range ----------------
template <int F, bool RELU, bool FINAL>
__global__ void k_aggregate(const float* __restrict__ H,
                            const float* __restrict__ bias,
                            float* __restrict__ out, int n0, int n1) {
    const int gw = (blockIdx.x * blockDim.x + threadIdx.x) >> 5;
    const int lane = threadIdx.x & 31;
    const int nwarps = (gridDim.x * blockDim.x) >> 5;
    const int c4 = lane * 4;
    const bool active = (F == 128) || (c4 < F);

    for (int i = n0 + gw; i < n1; i += nwarps) {
        float di = g_dinv[i];
        float sn = di * di;
        float4 acc = make_float4(0.f, 0.f, 0.f, 0.f);
        if (active) {
            float4 h = *(const float4*)(H + (size_t)i * F + c4);
            acc.x = sn * h.x; acc.y = sn * h.y; acc.z = sn * h.z; acc.w = sn * h.w;
        }
        const int beg = g_rowptr[i];
        const int end = g_rowptr[i + 1];
        for (int e = beg; e < end; e += 32) {
            int nb = end - e; if (nb > 32) nb = 32;
            int s = 0; float w = 0.f;
            if (lane < nb) {
                int2 sv = __ldg(&g_csr[e + lane]);
                s = sv.x;
                w = __int_as_float(sv.y);
            }
            int j = 0;
            for (; j + 4 <= nb; j += 4) {
                int   s0 = __shfl_sync(0xffffffffu, s, j + 0);
                int   s1 = __shfl_sync(0xffffffffu, s, j + 1);
                int   s2 = __shfl_sync(0xffffffffu, s, j + 2);
                int   s3 = __shfl_sync(0xffffffffu, s, j + 3);
                float w0 = __shfl_sync(0xffffffffu, w, j + 0);
                float w1 = __shfl_sync(0xffffffffu, w, j + 1);
                float w2 = __shfl_sync(0xffffffffu, w, j + 2);
                float w3 = __shfl_sync(0xffffffffu, w, j + 3);
                if (active) {
                    float4 h0 = __ldg((const float4*)(H + (size_t)s0 * F + c4));
                    float4 h1 = __ldg((const float4*)(H + (size_t)s1 * F + c4));
                    float4 h2 = __ldg((const float4*)(H + (size_t)s2 * F + c4));
                    float4 h3 = __ldg((const float4*)(H + (size_t)s3 * F + c4));
                    acc.x += w0 * h0.x; acc.y += w0 * h0.y; acc.z += w0 * h0.z; acc.w += w0 * h0.w;
                    acc.x += w1 * h1.x; acc.y += w1 * h1.y; acc.z += w1 * h1.z; acc.w += w1 * h1.w;
                    acc.x += w2 * h2.x; acc.y += w2 * h2.y; acc.z += w2 * h2.z; acc.w += w2 * h2.w;
                    acc.x += w3 * h3.x; acc.y += w3 * h3.y; acc.z += w3 * h3.z; acc.w += w3 * h3.w;
                }
            }
            for (; j < nb; ++j) {
                int   sj = __shfl_sync(0xffffffffu, s, j);
                float wj = __shfl_sync(0xffffffffu, w, j);
                if (active) {
                    float4 h = __ldg((const float4*)(H + (size_t)sj * F + c4));
                    acc.x += wj * h.x; acc.y += wj * h.y;
                    acc.z += wj * h.z; acc.w += wj * h.w;
                }
            }
        }
        if (active) {
            float4 b = *(const float4*)(bias + c4);
            acc.x += b.x; acc.y += b.y; acc.z += b.z; acc.w += b.w;
            if (RELU) {
                acc.x = fmaxf(acc.x, 0.f); acc.y = fmaxf(acc.y, 0.f);
                acc.z = fmaxf(acc.z, 0.f); acc.w = fmaxf(acc.w, 0.f);
            }
            if (!FINAL) {
                *(float4*)(out + (size_t)i * F + c4) = acc;
            } else {
                if (g_mint[i]) {
                    int p = g_outpos[i];
                    *(float4*)(out + (size_t)p * F + c4) = acc;
                }
            }
        }
    }
}

// ---------------- launch ----------------
extern "C" void kernel_launch(void* const* d_in, const int* in_sizes, int n_in,
                              void* d_out, int out_size) {
    const float *x = 0, *ew = 0, *W1 = 0, *b1 = 0, *W2 = 0, *b2 = 0, *W3 = 0, *b3 = 0;
    const void* ei = 0;
    const void* mask = 0;
    for (int i = 0; i < n_in; ++i) {
        switch (in_sizes[i]) {
            case 6400000: x = (const float*)d_in[i]; break;
            case 800000:  ew = (const float*)d_in[i]; break;
            case 16384:   if (!W1) W1 = (const float*)d_in[i]; else W2 = (const float*)d_in[i]; break;
            case 5120:    W3 = (const float*)d_in[i]; break;
            case 128:     if (!b1) b1 = (const float*)d_in[i]; else b2 = (const float*)d_in[i]; break;
            case 40:      b3 = (const float*)d_in[i]; break;
            case 1600000: ei = d_in[i]; break;
            case 50000:   mask = d_in[i]; break;
            default: break;
        }
    }
    float* out = (float*)d_out;

    static cudaStream_t s2 = 0;
    static cudaEvent_t evFork = 0, evJoin = 0, eA0 = 0, eB0 = 0, eA2 = 0, eB1 = 0;
    static bool init_done = false;
    if (!init_done) {
        cudaFuncSetAttribute(k_gemm128, cudaFuncAttributeMaxDynamicSharedMemorySize,
                             (128 * 128 + 64 * 128) * sizeof(float));
        cudaStreamCreateWithFlags(&s2, cudaStreamNonBlocking);
        cudaEventCreateWithFlags(&evFork, cudaEventDisableTiming);
        cudaEventCreateWithFlags(&evJoin, cudaEventDisableTiming);
        cudaEventCreateWithFlags(&eA0, cudaEventDisableTiming);
        cudaEventCreateWithFlags(&eB0, cudaEventDisableTiming);
        cudaEventCreateWithFlags(&eA2, cudaEventDisableTiming);
        cudaEventCreateWithFlags(&eB1, cudaEventDisableTiming);
        init_done = true;
    }

    float *hA, *hB, *hC;
    cudaGetSymbolAddress((void**)&hA, g_hA);
    cudaGetSymbolAddress((void**)&hB, g_hB);
    cudaGetSymbolAddress((void**)&hC, g_hC);

    const size_t smemG = (size_t)(128 * 128 + 64 * 128) * sizeof(float);
    const int gxH  = (HALF_N + 63) / 64;        // 391 blocks per half (GEMM128)
    const int gxF  = (N_NODES + 63) / 64;       // full-range GEMM (L1)
    const int gx32H = (HALF_N + 31) / 32;       // small GEMM half
    const int aggH = (HALF_N + 7) / 8;          // warp-per-node, half range
    const int aggF = (N_NODES + 7) / 8;         // full range (final layer)

    // ---- fork: GEMM L1 (independent of preprocessing) on side stream ----
    cudaEventRecord(evFork, 0);
    cudaStreamWaitEvent(s2, evFork, 0);
    k_gemm128<<<gxF, 256, smemG, s2>>>(x, W1, hA, 0, N_NODES);
    cudaEventRecord(evJoin, s2);

    // ---- preprocessing on main stream (concurrent with GEMM L1) ----
    k_prep0<<<NB_NODE, 256>>>(mask, ei);
    k_edge_prep<<<NB_EDGE, 256>>>(ei, ew);
    k_scan_fused<<<NB_NODE, 256>>>();
    k_scatter<<<NB_EDGE, 256>>>();

    // ---- pipelined tail: split agg->gemm pairs into halves across 2 streams ----
    cudaStreamWaitEvent(0, evJoin, 0);
    // layer 1 aggregate + layer 2 GEMM
    k_aggregate<128, true, false><<<aggH, 256>>>(hA, b1, hB, 0, HALF_N);
    cudaEventRecord(eA0, 0);
    cudaStreamWaitEvent(s2, eA0, 0);
    k_gemm128<<<gxH, 256, smemG, s2>>>(hB, W2, hA, 0, HALF_N);
    cudaEventRecord(eB0, s2);
    k_aggregate<128, true, false><<<aggH, 256>>>(hA, b1, hB, HALF_N, N_NODES);
    k_gemm128<<<gxH, 256, smemG>>>(hB, W2, hA, HALF_N, N_NODES);
    cudaStreamWaitEvent(0, eB0, 0);
    // layer 2 aggregate + layer 3 GEMM
    k_aggregate<128, true, false><<<aggH, 256>>>(hA, b2, hB, 0, HALF_N);
    cudaEventRecord(eA2, 0);
    cudaStreamWaitEvent(s2, eA2, 0);
    k_gemm_small<<<gx32H, 256, 0, s2>>>(hB, W3, hC, 0, HALF_N, 40);
    cudaEventRecord(eB1, s2);
    k_aggregate<128, true, false><<<aggH, 256>>>(hA, b2, hB, HALF_N, N_NODES);
    k_gemm_small<<<gx32H, 256>>>(hB, W3, hC, HALF_N, N_NODES, 40);
    cudaStreamWaitEvent(0, eB1, 0);
    // final aggregate (full range, masked compaction)
    k_aggregate<40, false, true><<<aggF, 256>>>(hC, b3, out, 0, N_NODES);
}

// round 10
// speedup vs baseline: 1.0307x; 1.0307x over previous
#include <cuda_runtime.h>
#include <stdint.h>

#define N_NODES 50000
#define N_EDGES 800000
#define F_HID 128
#define F_OUT 40
#define NB_NODE 196   /* ceil(50000/256) */
#define NB_EDGE 3125  /* 800000/256 */

// ---------------- device scratch ----------------
__device__ __align__(16) int   g_row[N_EDGES];
__device__ __align__(16) int   g_col[N_EDGES];
__device__ __align__(16) float g_ewc[N_EDGES];
__device__ __align__(16) float g_deg[N_NODES];
__device__ __align__(16) float g_dinv[N_NODES];
__device__ __align__(16) int   g_count[N_NODES];
__device__ __align__(16) int   g_fill[N_NODES];
__device__ __align__(16) int   g_mint[N_NODES];
__device__ __align__(16) int   g_rowptr[N_NODES + 1];
__device__ __align__(16) int   g_outpos[N_NODES];
__device__ volatile unsigned long long g_bsum[256];
__device__ __align__(16) int2  g_csr[N_EDGES];
__device__ __align__(16) float g_hA[(size_t)N_NODES * F_HID];
__device__ __align__(16) float g_hB[(size_t)N_NODES * F_HID];
__device__ __align__(16) float g_hC[(size_t)N_NODES * F_OUT];
__device__ int g_is64;

// ---------------- packed f32x2 helpers (Blackwell FFMA2) ----------------
__device__ __forceinline__ unsigned long long pack2(float lo, float hi) {
    unsigned long long r;
    asm("mov.b64 %0, {%1, %2};" : "=l"(r) : "f"(lo), "f"(hi));
    return r;
}
__device__ __forceinline__ void ffma2(unsigned long long& d,
                                      unsigned long long a,
                                      unsigned long long b) {
    asm("fma.rn.f32x2 %0, %1, %2, %0;" : "+l"(d) : "l"(a), "l"(b));
}
__device__ __forceinline__ float2 unpack2(unsigned long long v) {
    float lo, hi;
    asm("mov.b64 {%0, %1}, %2;" : "=f"(lo), "=f"(hi) : "l"(v));
    return make_float2(lo, hi);
}

// ---------------- fused init: probe + zero + mask decode ----------------
__global__ void k_prep0(const void* mask_, const void* ei_) {
    int i = blockIdx.x * blockDim.x + threadIdx.x;
    if (i == 0) {
        const long long* p = (const long long*)ei_;
        int ok = 1;
        #pragma unroll 1
        for (int k = 0; k < 64; ++k) {
            long long v = p[k];
            if (v < 0 || v >= N_NODES) { ok = 0; break; }
        }
        g_is64 = ok;
    }
    if (i < 256) g_bsum[i] = 0ull;
    if (i < N_NODES) {
        g_deg[i] = 0.0f;
        g_count[i] = 0;
        g_fill[i] = 0;
        unsigned int w0 = ((const unsigned int*)mask_)[0];
        int m;
        if (w0 == 1u) m = (((const int*)mask_)[i] != 0) ? 1 : 0;
        else          m = (((const unsigned char*)mask_)[i] != 0) ? 1 : 0;
        g_mint[i] = m;
    }
}

__global__ void k_edge_prep(const void* ei_, const float* __restrict__ ew) {
    int e = blockIdx.x * blockDim.x + threadIdx.x;
    if (e < N_EDGES) {
        int r, c;
        if (g_is64) {
            const long long* ei = (const long long*)ei_;
            r = (int)ei[e];
            c = (int)ei[N_EDGES + e];
        } else {
            const int* ei = (const int*)ei_;
            r = ei[e];
            c = ei[N_EDGES + e];
        }
        r = min(max(r, 0), N_NODES - 1);
        c = min(max(c, 0), N_NODES - 1);
        float w = ew[e];
        g_row[e] = r;
        g_col[e] = c;
        g_ewc[e] = w;
        atomicAdd(&g_deg[c], w);
        atomicAdd(&g_count[c], 1);
    }
}

// ---------------- single-kernel dual scan (decoupled lookback) ----------------
// Safe: 196 blocks all co-resident (256 thr, tiny smem); each block publishes
// its totals without waiting on any other block.
__global__ void k_scan_fused() {
    __shared__ int sa[256], sb[256];
    __shared__ int s_prefA, s_prefB;
    const int t = threadIdx.x;
    const int bid = blockIdx.x;
    const int i = bid * 256 + t;
    int va = (i < N_NODES) ? g_count[i] : 0;
    int vb = (i < N_NODES) ? g_mint[i] : 0;
    sa[t] = va; sb[t] = vb;
    __syncthreads();
    for (int off = 1; off < 256; off <<= 1) {
        int aa = (t >= off) ? sa[t - off] : 0;
        int ab = (t >= off) ? sb[t - off] : 0;
        __syncthreads();
        sa[t] += aa; sb[t] += ab;
        __syncthreads();
    }
    // publish packed block totals (flag = totalA+1 in low word; totals < 2^31)
    if (t == 255) {
        unsigned long long v = ((unsigned long long)(unsigned)sb[255] << 32)
                             | (unsigned)(sa[255] + 1);
        g_bsum[bid] = v;
    }
    // lookback over predecessors (warp 0)
    if (t < 32) {
        int pA = 0, pB = 0;
        for (int p = t; p < bid; p += 32) {
            unsigned long long v;
            do { v = g_bsum[p]; } while ((unsigned)v == 0u);
            pA += (int)((unsigned)v) - 1;
            pB += (int)(v >> 32);
        }
        #pragma unroll
        for (int off = 16; off > 0; off >>= 1) {
            pA += __shfl_down_sync(0xffffffffu, pA, off);
            pB += __shfl_down_sync(0xffffffffu, pB, off);
        }
        if (t == 0) { s_prefA = pA; s_prefB = pB; }
    }
    __syncthreads();
    if (i < N_NODES) {
        g_rowptr[i] = s_prefA + sa[t] - va;
        g_outpos[i] = s_prefB + sb[t] - vb;
        g_dinv[i] = rsqrtf(g_deg[i] + 1.0f);
    }
    if (bid == NB_NODE - 1 && t == 255) {
        g_rowptr[N_NODES] = s_prefA + sa[255];
    }
}

__global__ void k_scatter() {
    int e = blockIdx.x * blockDim.x + threadIdx.x;
    if (e < N_EDGES) {
        int c = g_col[e];
        int r = g_row[e];
        int pos = g_rowptr[c] + atomicAdd(&g_fill[c], 1);
        float nrm = g_dinv[r] * g_ewc[e] * g_dinv[c];
        g_csr[pos] = make_int2(r, __float_as_int(nrm));
    }
}

// ---------------- GEMM 128x128 (FFMA2) ----------------
__global__ void k_gemm128(const float* __restrict__ X, const float* __restrict__ W,
                          float* __restrict__ H, int M) {
    extern __shared__ float smdyn[];
    float* sW = smdyn;
    float* sX = smdyn + 128 * 128;
    const int tid = threadIdx.x;

    float4* sW4 = (float4*)sW;
    const float4* W4 = (const float4*)W;
    #pragma unroll
    for (int i = 0; i < 16; ++i) sW4[tid + 256 * i] = W4[tid + 256 * i];

    const int row0 = blockIdx.x * 64;
    float4* sX4 = (float4*)sX;
    #pragma unroll
    for (int i = 0; i < 8; ++i) {
        int idx = tid + 256 * i;
        int r = idx >> 5, c = idx & 31;
        int gr = min(row0 + r, M - 1);
        sX4[idx] = ((const float4*)(X + (size_t)gr * 128))[c];
    }
    __syncthreads();

    const int tx = tid & 15;
    const int ty = tid >> 4;

    unsigned long long acc[4][4];
    #pragma unroll
    for (int r = 0; r < 4; ++r)
        #pragma unroll
        for (int c = 0; c < 4; ++c) acc[r][c] = 0ull;

    const float* xbase = sX + (4 * ty) * 128;
    const float* wbase = sW + 8 * tx;

    #pragma unroll 4
    for (int k4 = 0; k4 < 32; ++k4) {
        float4 xr0 = *(const float4*)(xbase + 0 * 128 + 4 * k4);
        float4 xr1 = *(const float4*)(xbase + 1 * 128 + 4 * k4);
        float4 xr2 = *(const float4*)(xbase + 2 * 128 + 4 * k4);
        float4 xr3 = *(const float4*)(xbase + 3 * 128 + 4 * k4);
        #pragma unroll
        for (int kk = 0; kk < 4; ++kk) {
            const float* wrow = wbase + (4 * k4 + kk) * 128;
            ulonglong2 w01 = *(const ulonglong2*)(wrow);
            ulonglong2 w23 = *(const ulonglong2*)(wrow + 4);
            float x0 = (&xr0.x)[kk];
            float x1 = (&xr1.x)[kk];
            float x2 = (&xr2.x)[kk];
            float x3 = (&xr3.x)[kk];
            unsigned long long p0 = pack2(x0, x0);
            unsigned long long p1 = pack2(x1, x1);
            unsigned long long p2 = pack2(x2, x2);
            unsigned long long p3 = pack2(x3, x3);
            ffma2(acc[0][0], p0, w01.x); ffma2(acc[0][1], p0, w01.y);
            ffma2(acc[0][2], p0, w23.x); ffma2(acc[0][3], p0, w23.y);
            ffma2(acc[1][0], p1, w01.x); ffma2(acc[1][1], p1, w01.y);
            ffma2(acc[1][2], p1, w23.x); ffma2(acc[1][3], p1, w23.y);
            ffma2(acc[2][0], p2, w01.x); ffma2(acc[2][1], p2, w01.y);
            ffma2(acc[2][2], p2, w23.x); ffma2(acc[2][3], p2, w23.y);
            ffma2(acc[3][0], p3, w01.x); ffma2(acc[3][1], p3, w01.y);
            ffma2(acc[3][2], p3, w23.x); ffma2(acc[3][3], p3, w23.y);
        }
    }

    const int cg = 8 * tx;
    #pragma unroll
    for (int r = 0; r < 4; ++r) {
        int gr = row0 + 4 * ty + r;
        if (gr < M) {
            float2 q0 = unpack2(acc[r][0]);
            float2 q1 = unpack2(acc[r][1]);
            float2 q2 = unpack2(acc[r][2]);
            float2 q3 = unpack2(acc[r][3]);
            float4* dst = (float4*)(H + (size_t)gr * 128 + cg);
            dst[0] = make_float4(q0.x, q0.y, q1.x, q1.y);
            dst[1] = make_float4(q2.x, q2.y, q3.x, q3.y);
        }
    }
}

// ---------------- GEMM small-N (layer 3, N=40) ----------------
__global__ void k_gemm_small(const float* __restrict__ X, const float* __restrict__ W,
                             float* __restrict__ H, int M, int N) {
    __shared__ float sW[128 * 64];
    const int tid = threadIdx.x;
    const int sw = N;

    for (int i = tid; i < 128 * sw; i += 256) {
        int k = i / sw, c = i - k * sw;
        sW[k * 64 + c] = W[k * N + c];
    }
    __syncthreads();

    const int warp = tid >> 5;
    const int lane = tid & 31;
    const int r0 = blockIdx.x * 32 + warp * 4;
    const int myc = lane * 2;
    if (myc >= sw) return;

    const float* x0 = X + (size_t)min(r0 + 0, M - 1) * 128;
    const float* x1 = X + (size_t)min(r0 + 1, M - 1) * 128;
    const float* x2 = X + (size_t)min(r0 + 2, M - 1) * 128;
    const float* x3 = X + (size_t)min(r0 + 3, M - 1) * 128;

    float2 a0 = {0.f, 0.f}, a1 = a0, a2 = a0, a3 = a0;
    #pragma unroll 8
    for (int k = 0; k < 128; ++k) {
        float w0 = sW[k * 64 + myc];
        float w1 = sW[k * 64 + myc + 1];
        float v0 = __ldg(x0 + k), v1 = __ldg(x1 + k);
        float v2 = __ldg(x2 + k), v3 = __ldg(x3 + k);
        a0.x += v0 * w0; a0.y += v0 * w1;
        a1.x += v1 * w0; a1.y += v1 * w1;
        a2.x += v2 * w0; a2.y += v2 * w1;
        a3.x += v3 * w0; a3.y += v3 * w1;
    }

    if (r0 + 0 < M) *(float2*)(H + (size_t)(r0 + 0) * N + myc) = a0;
    if (r0 + 1 < M) *(float2*)(H + (size_t)(r0 + 1) * N + myc) = a1;
    if (r0 + 2 < M) *(float2*)(H + (size_t)(r0 + 2) * N + myc) = a2;
    if (r0 + 3 < M) *(float2*)(H + (size_t)(r0 + 3) * N + myc) = a3;
}

// ---------------- pull aggregation (warp/node, float4, x4 unroll) ----------------
template <int F, bool RELU, bool FINAL>
__global__ void k_aggregate(const float* __restrict__ H,
                            const float* __restrict__ bias,
                            float* __restrict__ out) {
    const int gw = (blockIdx.x * blockDim.x + threadIdx.x) >> 5;
    const int lane = threadIdx.x & 31;
    const int nwarps = (gridDim.x * blockDim.x) >> 5;
    const int c4 = lane * 4;
    const bool active = (F == 128) || (c4 < F);

    for (int i = gw; i < N_NODES; i += nwarps) {
        float di = g_dinv[i];
        float sn = di * di;
        float4 acc = make_float4(0.f, 0.f, 0.f, 0.f);
        if (active) {
            float4 h = *(const float4*)(H + (size_t)i * F + c4);
            acc.x = sn * h.x; acc.y = sn * h.y; acc.z = sn * h.z; acc.w = sn * h.w;
        }
        const int beg = g_rowptr[i];
        const int end = g_rowptr[i + 1];
        for (int e = beg; e < end; e += 32) {
            int nb = end - e; if (nb > 32) nb = 32;
            int s = 0; float w = 0.f;
            if (lane < nb) {
                int2 sv = __ldg(&g_csr[e + lane]);
                s = sv.x;
                w = __int_as_float(sv.y);
            }
            int j = 0;
            for (; j + 4 <= nb; j += 4) {
                int   s0 = __shfl_sync(0xffffffffu, s, j + 0);
                int   s1 = __shfl_sync(0xffffffffu, s, j + 1);
                int   s2 = __shfl_sync(0xffffffffu, s, j + 2);
                int   s3 = __shfl_sync(0xffffffffu, s, j + 3);
                float w0 = __shfl_sync(0xffffffffu, w, j + 0);
                float w1 = __shfl_sync(0xffffffffu, w, j + 1);
                float w2 = __shfl_sync(0xffffffffu, w, j + 2);
                float w3 = __shfl_sync(0xffffffffu, w, j + 3);
                if (active) {
                    float4 h0 = __ldg((const float4*)(H + (size_t)s0 * F + c4));
                    float4 h1 = __ldg((const float4*)(H + (size_t)s1 * F + c4));
                    float4 h2 = __ldg((const float4*)(H + (size_t)s2 * F + c4));
                    float4 h3 = __ldg((const float4*)(H + (size_t)s3 * F + c4));
                    acc.x += w0 * h0.x; acc.y += w0 * h0.y; acc.z += w0 * h0.z; acc.w += w0 * h0.w;
                    acc.x += w1 * h1.x; acc.y += w1 * h1.y; acc.z += w1 * h1.z; acc.w += w1 * h1.w;
                    acc.x += w2 * h2.x; acc.y += w2 * h2.y; acc.z += w2 * h2.z; acc.w += w2 * h2.w;
                    acc.x += w3 * h3.x; acc.y += w3 * h3.y; acc.z += w3 * h3.z; acc.w += w3 * h3.w;
                }
            }
            for (; j < nb; ++j) {
                int   sj = __shfl_sync(0xffffffffu, s, j);
                float wj = __shfl_sync(0xffffffffu, w, j);
                if (active) {
                    float4 h = __ldg((const float4*)(H + (size_t)sj * F + c4));
                    acc.x += wj * h.x; acc.y += wj * h.y;
                    acc.z += wj * h.z; acc.w += wj * h.w;
                }
            }
        }
        if (active) {
            float4 b = *(const float4*)(bias + c4);
            acc.x += b.x; acc.y += b.y; acc.z += b.z; acc.w += b.w;
            if (RELU) {
                acc.x = fmaxf(acc.x, 0.f); acc.y = fmaxf(acc.y, 0.f);
                acc.z = fmaxf(acc.z, 0.f); acc.w = fmaxf(acc.w, 0.f);
            }
            if (!FINAL) {
                *(float4*)(out + (size_t)i * F + c4) = acc;
            } else {
                if (g_mint[i]) {
                    int p = g_outpos[i];
                    *(float4*)(out + (size_t)p * F + c4) = acc;
                }
            }
        }
    }
}

// ---------------- launch ----------------
extern "C" void kernel_launch(void* const* d_in, const int* in_sizes, int n_in,
                              void* d_out, int out_size) {
    const float *x = 0, *ew = 0, *W1 = 0, *b1 = 0, *W2 = 0, *b2 = 0, *W3 = 0, *b3 = 0;
    const void* ei = 0;
    const void* mask = 0;
    for (int i = 0; i < n_in; ++i) {
        switch (in_sizes[i]) {
            case 6400000: x = (const float*)d_in[i]; break;
            case 800000:  ew = (const float*)d_in[i]; break;
            case 16384:   if (!W1) W1 = (const float*)d_in[i]; else W2 = (const float*)d_in[i]; break;
            case 5120:    W3 = (const float*)d_in[i]; break;
            case 128:     if (!b1) b1 = (const float*)d_in[i]; else b2 = (const float*)d_in[i]; break;
            case 40:      b3 = (const float*)d_in[i]; break;
            case 1600000: ei = d_in[i]; break;
            case 50000:   mask = d_in[i]; break;
            default: break;
        }
    }
    float* out = (float*)d_out;

    static cudaStream_t s2 = 0;
    static cudaEvent_t evFork = 0, evJoin = 0;
    static bool init_done = false;
    if (!init_done) {
        cudaFuncSetAttribute(k_gemm128, cudaFuncAttributeMaxDynamicSharedMemorySize,
                             (128 * 128 + 64 * 128) * sizeof(float));
        cudaStreamCreateWithFlags(&s2, cudaStreamNonBlocking);
        cudaEventCreateWithFlags(&evFork, cudaEventDisableTiming);
        cudaEventCreateWithFlags(&evJoin, cudaEventDisableTiming);
        init_done = true;
    }

    float *hA, *hB, *hC;
    cudaGetSymbolAddress((void**)&hA, g_hA);
    cudaGetSymbolAddress((void**)&hB, g_hB);
    cudaGetSymbolAddress((void**)&hC, g_hC);

    const size_t smemG = (size_t)(128 * 128 + 64 * 128) * sizeof(float);
    const int gx128 = (N_NODES + 63) / 64;
    const int gx32  = (N_NODES + 31) / 32;
    const int agg_blocks = (N_NODES + 7) / 8;   // warp per node

    // ---- fork: GEMM L1 (independent of graph preprocessing) on side stream ----
    cudaEventRecord(evFork, 0);
    cudaStreamWaitEvent(s2, evFork, 0);
    k_gemm128<<<gx128, 256, smemG, s2>>>(x, W1, hA, N_NODES);
    cudaEventRecord(evJoin, s2);

    // ---- preprocessing chain on main stream (concurrent with GEMM L1) ----
    k_prep0<<<NB_NODE, 256>>>(mask, ei);
    k_edge_prep<<<NB_EDGE, 256>>>(ei, ew);
    k_scan_fused<<<NB_NODE, 256>>>();
    k_scatter<<<NB_EDGE, 256>>>();

    // ---- join, then the serial tail (R8-proven structure) ----
    cudaStreamWaitEvent(0, evJoin, 0);
    k_aggregate<128, true, false><<<agg_blocks, 256>>>(hA, b1, hB);
    k_gemm128<<<gx128, 256, smemG>>>(hB, W2, hA, N_NODES);
    k_aggregate<128, true, false><<<agg_blocks, 256>>>(hA, b2, hB);
    k_gemm_small<<<gx32, 256>>>(hB, W3, hC, N_NODES, 40);
    k_aggregate<40, false, true><<<agg_blocks, 256>>>(hC, b3, out);
}